// round 14
// baseline (speedup 1.0000x reference)
#include <cuda_runtime.h>
#include <cuda_bf16.h>
#include <math.h>

// ---------------------------------------------------------------------------
// Problem constants
// ---------------------------------------------------------------------------
#define NQ      16
#define DIM     1024
#define NDB     400000
#define RB      256                       // rows per tile
#define NBLK    ((NDB + RB - 1) / RB)     // 1563 tiles
#define NSTG    16                        // K-stages of 64 floats
#define EPSV    1e-8f
#define GRID    152
#define T       512                       // 8 consumer + 8 producer warps

// Query smem: padded bf16 rows, stride 2080 B (conflict-free LDS.64)
#define QSTRIDE_B  2080
#define QMAT_B     (NQ * QSTRIDE_B)       // 33280
#define QTOT_B     (2 * QMAT_B)           // 66560
// Ring: 4 slots x (128 rows x 256 B), XOR-4 unit swizzle
#define STG_B      32768
#define OFF_STG    QTOT_B
#define OFF_SCR    (OFF_STG + 4 * STG_B)  // 197632
#define SMEM_TOTAL (OFF_SCR + 2048)       // 199680 B

typedef unsigned int       u32;
typedef unsigned long long u64;

// ---------------------------------------------------------------------------
// Device scratch
// ---------------------------------------------------------------------------
__device__ __align__(16) char g_qB[QTOT_B];   // hi/lo padded bf16 queries
__device__ u64      g_pkey[NBLK * NQ];
__device__ float    g_psum[NBLK * NQ];
__device__ unsigned g_ctr;

// ---------------------------------------------------------------------------
// Helpers
// ---------------------------------------------------------------------------
__device__ __forceinline__ u32 cvtpack(float hi, float lo) {
    __nv_bfloat162 h = __floats2bfloat162_rn(lo, hi);
    return *(u32*)&h;
}
__device__ __forceinline__ float lo2f(u32 p) { return __uint_as_float(p << 16); }
__device__ __forceinline__ float hi2f(u32 p) { return __uint_as_float(p & 0xFFFF0000u); }

__device__ __forceinline__ void mma16816(float* d, const u32* a, const u32* b) {
    asm volatile(
        "mma.sync.aligned.m16n8k16.row.col.f32.bf16.bf16.f32 "
        "{%0,%1,%2,%3}, {%4,%5,%6,%7}, {%8,%9}, {%0,%1,%2,%3};"
        : "+f"(d[0]), "+f"(d[1]), "+f"(d[2]), "+f"(d[3])
        : "r"(a[0]), "r"(a[1]), "r"(a[2]), "r"(a[3]), "r"(b[0]), "r"(b[1]));
}
__device__ __forceinline__ u64 pack_key(float f, int idx) {
    unsigned b = __float_as_uint(f);
    unsigned o = (b & 0x80000000u) ? ~b : (b | 0x80000000u);
    return ((u64)o << 32) | (unsigned)(~(unsigned)idx);
}
__device__ __forceinline__ void cp16(u32 dst, const void* src) {
    asm volatile("cp.async.cg.shared.global [%0], [%1], 16;" :: "r"(dst), "l"(src));
}
__device__ __forceinline__ u32 smem_u32(const void* p) {
    u32 a;
    asm("{ .reg .u64 t; cvta.to.shared.u64 t, %1; cvt.u32.u64 %0, t; }"
        : "=r"(a) : "l"(p));
    return a;
}
#define MBAR_INIT(addr, cnt) \
    asm volatile("mbarrier.init.shared.b64 [%0], %1;" :: "r"(addr), "r"(cnt) : "memory")
#define MBAR_ARRIVE(addr) \
    asm volatile("mbarrier.arrive.shared.b64 _, [%0];" :: "r"(addr) : "memory")
#define CPASYNC_ARRIVE(addr) \
    asm volatile("cp.async.mbarrier.arrive.noinc.shared.b64 [%0];" :: "r"(addr) : "memory")
#define MBAR_WAIT(addr, parity) do {                                              \
    u32 _m = (addr), _p = (u32)(parity), _done;                                   \
    asm volatile("{\n\t.reg .pred p;\n\t"                                         \
        "mbarrier.try_wait.parity.acquire.cta.shared::cta.b64 p, [%1], %2;\n\t"   \
        "selp.b32 %0, 1, 0, p;\n\t}" : "=r"(_done) : "r"(_m), "r"(_p) : "memory");\
    if (!_done) {                                                                 \
        asm volatile("{\n\t.reg .pred P1;\n\t"                                    \
            "WL_%=:\n\t"                                                          \
            "mbarrier.try_wait.parity.acquire.cta.shared::cta.b64 P1, [%0], %1, 0x989680;\n\t" \
            "@P1 bra.uni WD_%=;\n\tbra.uni WL_%=;\n\tWD_%=:\n\t}"                 \
            :: "r"(_m), "r"(_p) : "memory");                                      \
    }                                                                             \
} while (0)

// ---------------------------------------------------------------------------
// Kernel 1: normalize queries, bf16 hi/lo split, padded store; reset counter
// ---------------------------------------------------------------------------
__global__ void qprep_kernel(const float* __restrict__ q) {
    const int b = blockIdx.x;
    const int t = threadIdx.x;               // 256 threads x 4 floats
    if (b == 0 && t == 0) g_ctr = 0;

    float4 v = *(const float4*)(q + b * DIM + t * 4);
    float s = v.x * v.x + v.y * v.y + v.z * v.z + v.w * v.w;

    __shared__ float red[8];
    __shared__ float invn;
    #pragma unroll
    for (int o = 16; o; o >>= 1) s += __shfl_xor_sync(0xFFFFFFFFu, s, o);
    if ((t & 31) == 0) red[t >> 5] = s;
    __syncthreads();
    if (t == 0) {
        float tot = 0.f;
        #pragma unroll
        for (int i = 0; i < 8; i++) tot += red[i];
        invn = 1.f / (sqrtf(tot) + EPSV);
    }
    __syncthreads();
    float iv = invn;
    float x0 = v.x * iv, x1 = v.y * iv, x2 = v.z * iv, x3 = v.w * iv;

    u32 h0 = cvtpack(x1, x0), h1 = cvtpack(x3, x2);
    float e0 = x0 - lo2f(h0), e1 = x1 - hi2f(h0);
    float e2 = x2 - lo2f(h1), e3 = x3 - hi2f(h1);
    u32 l0 = cvtpack(e1, e0), l1 = cvtpack(e3, e2);

    char* dh = g_qB + b * QSTRIDE_B + t * 8;
    *(uint2*)dh            = make_uint2(h0, h1);
    *(uint2*)(dh + QMAT_B) = make_uint2(l0, l1);
    if (t < 4) {
        *(uint2*)(g_qB + b * QSTRIDE_B + 2048 + t * 8)          = make_uint2(0, 0);
        *(uint2*)(g_qB + b * QSTRIDE_B + 2048 + t * 8 + QMAT_B) = make_uint2(0, 0);
    }
}

// ---------------------------------------------------------------------------
// Producer slot fill: 128 rows x 64 floats, 256B-per-row coalesced bursts
// ---------------------------------------------------------------------------
__device__ __forceinline__ void fill_slot(const float* __restrict__ db, u32 sb,
                                          int tile, int s, int h, int slot,
                                          int pt) {
    const u32 base = sb + OFF_STG + (u32)slot * STG_B;
    const int rowBase = tile * RB + h * 128;
    #pragma unroll
    for (int i = 0; i < 8; i++) {
        int idx = i * 256 + pt;             // 16 consecutive lanes = one 256B row
        int row = idx >> 4, u = idx & 15;
        int up = u ^ ((row & 1) << 2);
        long long gr = rowBase + row;
        if (gr > NDB - 1) gr = NDB - 1;
        const float* src = db + gr * (long long)DIM + s * 64 + u * 4;
        cp16(base + (u32)(row * 256 + up * 16), src);
    }
}

// ---------------------------------------------------------------------------
// Kernel 2: warp-specialized persistent similarity kernel
// ---------------------------------------------------------------------------
__global__ void __launch_bounds__(T, 1)
sim_kernel(const float* __restrict__ db) {
    extern __shared__ char smem[];
    const u32 sb = smem_u32(smem);
    const int t = threadIdx.x;
    const int w = t >> 5, lane = t & 31;
    const int rq = lane >> 2, c = lane & 3;
    const u32 xr = (u32)((rq & 1) << 2);

    u64*   skey = (u64*)(smem + OFF_SCR);                 // [16][8]
    float* ssum = (float*)(smem + OFF_SCR + 1024);        // [16][8]
    volatile int* tileRing = (volatile int*)(smem + OFF_SCR + 1536);  // [8]
    const u32 mb_full  = sb + OFF_SCR + 1600;             // 4 x 8B
    const u32 mb_empty = sb + OFF_SCR + 1632;             // 4 x 8B

    // ---- Q copy into smem ----
    #pragma unroll
    for (int i = 0; i < 9; i++) {
        int ch = t + i * T;
        if (ch < QTOT_B / 16)
            cp16(sb + (u32)ch * 16u, g_qB + (size_t)ch * 16);
    }
    asm volatile("cp.async.commit_group;");
    if (t == 0) {
        #pragma unroll
        for (int i = 0; i < 4; i++) {
            MBAR_INIT(mb_full + i * 8, 256u);    // producers: 256 noinc arrives
            MBAR_INIT(mb_empty + i * 8, 128u);   // consumers: 128 arrives
        }
    }
    asm volatile("cp.async.wait_group 0;");
    __syncthreads();

    if (w >= 8) {
        // =================== PRODUCER (warps 8-15) ===================
        const int pt = t - 256;
        int ep0 = 1, ep1 = 1, ep2 = 1, ep3 = 1;
        int n = 0;
        for (;;) {
            if (t == 256) tileRing[n & 7] = (int)atomicAdd(&g_ctr, 1u);
            __threadfence_block();
            asm volatile("bar.sync 2, 256;" ::: "memory");
            int tile = tileRing[n & 7];
            if (tile >= NBLK) {
                MBAR_WAIT(mb_empty + 0, ep0);
                MBAR_ARRIVE(mb_full + 0);
                MBAR_WAIT(mb_empty + 8, ep1);
                MBAR_ARRIVE(mb_full + 8);
                break;
            }
            #pragma unroll 1
            for (int su = 0; su < NSTG; su += 2) {
                MBAR_WAIT(mb_empty + 0,  ep0); ep0 ^= 1;
                fill_slot(db, sb, tile, su,     0, 0, pt);
                CPASYNC_ARRIVE(mb_full + 0);
                MBAR_WAIT(mb_empty + 8,  ep1); ep1 ^= 1;
                fill_slot(db, sb, tile, su,     1, 1, pt);
                CPASYNC_ARRIVE(mb_full + 8);
                MBAR_WAIT(mb_empty + 16, ep2); ep2 ^= 1;
                fill_slot(db, sb, tile, su + 1, 0, 2, pt);
                CPASYNC_ARRIVE(mb_full + 16);
                MBAR_WAIT(mb_empty + 24, ep3); ep3 ^= 1;
                fill_slot(db, sb, tile, su + 1, 1, 3, pt);
                CPASYNC_ARRIVE(mb_full + 24);
            }
            n++;
        }
    } else {
        // =================== CONSUMER (warps 0-7) ===================
        const int h = w >> 2;                   // row-half -> slot parity class
        const char* bh[2];
        const char* bl[2];
        bh[0] = smem + rq * QSTRIDE_B + c * 8;
        bh[1] = bh[0] + 8 * QSTRIDE_B;
        bl[0] = bh[0] + QMAT_B;
        bl[1] = bh[1] + QMAT_B;
        u32 rowoff[4];
        int rloc[4];
        #pragma unroll
        for (int i = 0; i < 4; i++) {
            rloc[i] = w * 32 + rq + i * 8;                    // tile-row
            rowoff[i] = (u32)((rloc[i] - h * 128) * 256);     // slot-local
        }
        const char* baseA = smem + OFF_STG + (size_t)h * STG_B;
        const char* baseB = baseA + 2 * STG_B;
        const u32 fullA  = mb_full  + (u32)h * 8;
        const u32 fullB  = fullA + 16;
        const u32 emptyA = mb_empty + (u32)h * 8;
        const u32 emptyB = emptyA + 16;
        int fpA = 0, fpB = 0;
        int n = 0;

        for (;;) {
            float d[2][2][4];
            float nrm[4] = {0.f, 0.f, 0.f, 0.f};
            #pragma unroll
            for (int m = 0; m < 2; m++)
                #pragma unroll
                for (int nt = 0; nt < 2; nt++)
                    #pragma unroll
                    for (int j = 0; j < 4; j++) d[m][nt][j] = 0.f;

            int tile = 0;
            #pragma unroll 1
            for (int s2 = 0; s2 < NSTG; s2 += 2) {
                // ---- even stage from slot class A ----
                MBAR_WAIT(fullA, fpA); fpA ^= 1;
                if (s2 == 0) {
                    tile = tileRing[n & 7];
                    if (tile >= NBLK) break;
                }
                #pragma unroll
                for (int half = 0; half < 2; half++) {
                    const char* A = half ? baseB : baseA;
                    const int s = s2 + half;
                    if (half) { MBAR_WAIT(fullB, fpB); fpB ^= 1; }
                    #pragma unroll
                    for (int j = 0; j < 4; j++) {
                        const int ch = s * 4 + j;
                        const u32 uoff = (u32)((((u32)(j * 4 + c)) ^ xr) * 16u);
                        float4 av[4];
                        #pragma unroll
                        for (int i = 0; i < 4; i++)
                            av[i] = *(const float4*)(A + rowoff[i] + uoff);
                        u32 ah[2][4], al[2][4];
                        #pragma unroll
                        for (int m = 0; m < 2; m++) {
                            float4 f = av[2 * m], g = av[2 * m + 1];
                            nrm[2 * m]     += f.x * f.x + f.y * f.y + f.z * f.z + f.w * f.w;
                            nrm[2 * m + 1] += g.x * g.x + g.y * g.y + g.z * g.z + g.w * g.w;
                            u32 fh0 = cvtpack(f.y, f.x), fh1 = cvtpack(f.w, f.z);
                            u32 gh0 = cvtpack(g.y, g.x), gh1 = cvtpack(g.w, g.z);
                            ah[m][0] = fh0; ah[m][1] = gh0; ah[m][2] = fh1; ah[m][3] = gh1;
                            float e0 = f.x - lo2f(fh0), e1 = f.y - hi2f(fh0);
                            float e2 = f.z - lo2f(fh1), e3 = f.w - hi2f(fh1);
                            float u0 = g.x - lo2f(gh0), u1 = g.y - hi2f(gh0);
                            float u2 = g.z - lo2f(gh1), u3 = g.w - hi2f(gh1);
                            al[m][0] = cvtpack(e1, e0); al[m][1] = cvtpack(u1, u0);
                            al[m][2] = cvtpack(e3, e2); al[m][3] = cvtpack(u3, u2);
                        }
                        #pragma unroll
                        for (int nt = 0; nt < 2; nt++) {
                            uint2 vh = *(const uint2*)(bh[nt] + ch * 32);
                            uint2 vl = *(const uint2*)(bl[nt] + ch * 32);
                            u32 bhf[2] = {vh.x, vh.y};
                            u32 blf[2] = {vl.x, vl.y};
                            #pragma unroll
                            for (int m = 0; m < 2; m++) {
                                mma16816(d[m][nt], ah[m], bhf);
                                mma16816(d[m][nt], ah[m], blf);
                                mma16816(d[m][nt], al[m], bhf);
                            }
                        }
                    }
                    MBAR_ARRIVE(half ? emptyB : emptyA);
                }
            }
            if (tile >= NBLK) break;

            // ---- epilogue (consumer-only named barrier) ----
            float inv[4];
            #pragma unroll
            for (int j = 0; j < 4; j++) {
                float nn = nrm[j];
                nn += __shfl_xor_sync(0xFFFFFFFFu, nn, 1);
                nn += __shfl_xor_sync(0xFFFFFFFFu, nn, 2);
                inv[j] = 1.f / (sqrtf(nn) + EPSV);
            }
            int  grow[4];
            bool valid[4];
            #pragma unroll
            for (int j = 0; j < 4; j++) {
                grow[j] = tile * RB + rloc[j];
                valid[j] = grow[j] < NDB;
            }
            #pragma unroll
            for (int nt = 0; nt < 2; nt++)
                #pragma unroll
                for (int j = 0; j < 2; j++) {
                    int q = nt * 8 + 2 * c + j;
                    float s0 = d[0][nt][j]     * inv[0];
                    float s1 = d[0][nt][2 + j] * inv[1];
                    float s2v = d[1][nt][j]     * inv[2];
                    float s3 = d[1][nt][2 + j] * inv[3];
                    u64 kb = 0ull; float sm = 0.f;
                    if (valid[0]) { u64 k = pack_key(s0, grow[0]); if (k > kb) kb = k; sm += s0; }
                    if (valid[1]) { u64 k = pack_key(s1, grow[1]); if (k > kb) kb = k; sm += s1; }
                    if (valid[2]) { u64 k = pack_key(s2v, grow[2]); if (k > kb) kb = k; sm += s2v; }
                    if (valid[3]) { u64 k = pack_key(s3, grow[3]); if (k > kb) kb = k; sm += s3; }
                    #pragma unroll
                    for (int o = 4; o <= 16; o <<= 1) {
                        u64   ok = __shfl_xor_sync(0xFFFFFFFFu, kb, o);
                        float os = __shfl_xor_sync(0xFFFFFFFFu, sm, o);
                        if (ok > kb) kb = ok;
                        sm += os;
                    }
                    if (rq == 0) { skey[q * 8 + w] = kb; ssum[q * 8 + w] = sm; }
                }
            asm volatile("bar.sync 1, 256;" ::: "memory");
            if (t < 128) {
                int q = t >> 3, w2 = t & 7;
                u64 kb = skey[q * 8 + w2];
                float sm = ssum[q * 8 + w2];
                #pragma unroll
                for (int o = 4; o; o >>= 1) {
                    u64   ok = __shfl_down_sync(0xFFFFFFFFu, kb, o, 8);
                    float os = __shfl_down_sync(0xFFFFFFFFu, sm, o, 8);
                    if (ok > kb) kb = ok;
                    sm += os;
                }
                if (w2 == 0) {
                    g_pkey[(size_t)tile * NQ + q] = kb;
                    g_psum[(size_t)tile * NQ + q] = sm;
                }
            }
            asm volatile("bar.sync 1, 256;" ::: "memory");
            n++;
        }
    }
}

// ---------------------------------------------------------------------------
// Kernel 3: finalize
// ---------------------------------------------------------------------------
__global__ void finalize_kernel(const int* __restrict__ db_classes,
                                const int* __restrict__ y,
                                float* __restrict__ out) {
    const int t = threadIdx.x;        // 256
    const int q = t >> 4, sub = t & 15;

    u64 kb = 0ull; float sm = 0.f;
    for (int i = sub; i < NBLK; i += 16) {
        u64 k = g_pkey[(size_t)i * NQ + q];
        if (k > kb) kb = k;
        sm += g_psum[(size_t)i * NQ + q];
    }
    #pragma unroll
    for (int o = 8; o; o >>= 1) {
        u64   ok = __shfl_down_sync(0xFFFFFFFFu, kb, o, 16);
        float os = __shfl_down_sync(0xFFFFFFFFu, sm, o, 16);
        if (ok > kb) kb = ok;
        sm += os;
    }

    __shared__ u64   skey[NQ];
    __shared__ float ssum[NQ];
    __shared__ int   scls[NQ];
    if (sub == 0) { skey[q] = kb; ssum[q] = sm; }
    __syncthreads();

    if (t < NQ) {
        u64 k = skey[t];
        unsigned idx = ~((unsigned)k);
        unsigned o   = (unsigned)(k >> 32);
        unsigned fb  = (o & 0x80000000u) ? (o & 0x7FFFFFFFu) : ~o;
        float mx = __uint_as_float(fb);
        int cls = db_classes[idx];
        out[t]          = mx;
        out[NQ + t]     = ssum[t] / (float)NDB;
        out[2 * NQ + t] = (float)cls;
        scls[t] = cls;
    }
    __syncthreads();
    if (t == 0) {
        int cnt = 0;
        #pragma unroll
        for (int i = 0; i < NQ; i++) cnt += (scls[i] == y[i]) ? 1 : 0;
        out[3 * NQ] = (float)cnt / (float)NQ;
    }
}

// ---------------------------------------------------------------------------
// kernel_launch
// ---------------------------------------------------------------------------
extern "C" void kernel_launch(void* const* d_in, const int* in_sizes, int n_in,
                              void* d_out, int out_size) {
    const float* queries    = (const float*)d_in[0];
    const float* database   = (const float*)d_in[1];
    const int*   db_classes = (const int*)d_in[2];
    const int*   y          = (const int*)d_in[3];
    float* out = (float*)d_out;

    cudaFuncSetAttribute(sim_kernel,
                         cudaFuncAttributeMaxDynamicSharedMemorySize,
                         SMEM_TOTAL);

    qprep_kernel<<<NQ, 256>>>(queries);
    sim_kernel<<<GRID, T, SMEM_TOTAL>>>(database);
    finalize_kernel<<<1, 256>>>(db_classes, y, out);
}

// round 15
// speedup vs baseline: 1.1886x; 1.1886x over previous
#include <cuda_runtime.h>
#include <cuda_bf16.h>
#include <math.h>

// ---------------------------------------------------------------------------
// Problem constants
// ---------------------------------------------------------------------------
#define NQ      16
#define DIM     1024
#define NDB     400000
#define RB      256                       // rows per tile
#define NBLK    ((NDB + RB - 1) / RB)     // 1563 tiles
#define NSTG    16                        // K-stages of 64 floats
#define EPSV    1e-8f
#define GRID    152
#define T       512                       // 8 consumer + 8 producer warps

// Query smem: padded bf16 rows, stride 2080 B (conflict-free LDS.64)
#define QSTRIDE_B  2080
#define QMAT_B     (NQ * QSTRIDE_B)       // 33280
#define QTOT_B     (2 * QMAT_B)           // 66560
// Ring: 4 slots x (128 rows x 256 B), XOR-4 unit swizzle
#define STG_B      32768
#define OFF_STG    QTOT_B
#define OFF_SCR    (OFF_STG + 4 * STG_B)  // 197632
#define SMEM_TOTAL (OFF_SCR + 2048)       // 199680 B

typedef unsigned int       u32;
typedef unsigned long long u64;

// ---------------------------------------------------------------------------
// Device scratch
// ---------------------------------------------------------------------------
__device__ u64      g_pkey[NBLK * NQ];
__device__ float    g_psum[NBLK * NQ];
__device__ unsigned g_ctr  = 0;
__device__ unsigned g_done = 0;

// ---------------------------------------------------------------------------
// Helpers
// ---------------------------------------------------------------------------
__device__ __forceinline__ u32 cvtpack(float hi, float lo) {
    __nv_bfloat162 h = __floats2bfloat162_rn(lo, hi);
    return *(u32*)&h;
}
__device__ __forceinline__ float lo2f(u32 p) { return __uint_as_float(p << 16); }
__device__ __forceinline__ float hi2f(u32 p) { return __uint_as_float(p & 0xFFFF0000u); }

__device__ __forceinline__ void mma16816(float* d, const u32* a, const u32* b) {
    asm volatile(
        "mma.sync.aligned.m16n8k16.row.col.f32.bf16.bf16.f32 "
        "{%0,%1,%2,%3}, {%4,%5,%6,%7}, {%8,%9}, {%0,%1,%2,%3};"
        : "+f"(d[0]), "+f"(d[1]), "+f"(d[2]), "+f"(d[3])
        : "r"(a[0]), "r"(a[1]), "r"(a[2]), "r"(a[3]), "r"(b[0]), "r"(b[1]));
}
__device__ __forceinline__ u64 pack_key(float f, int idx) {
    unsigned b = __float_as_uint(f);
    unsigned o = (b & 0x80000000u) ? ~b : (b | 0x80000000u);
    return ((u64)o << 32) | (unsigned)(~(unsigned)idx);
}
__device__ __forceinline__ void cp16(u32 dst, const void* src) {
    asm volatile("cp.async.cg.shared.global [%0], [%1], 16;" :: "r"(dst), "l"(src));
}
__device__ __forceinline__ u32 smem_u32(const void* p) {
    u32 a;
    asm("{ .reg .u64 t; cvta.to.shared.u64 t, %1; cvt.u32.u64 %0, t; }"
        : "=r"(a) : "l"(p));
    return a;
}
#define MBAR_INIT(addr, cnt) \
    asm volatile("mbarrier.init.shared.b64 [%0], %1;" :: "r"(addr), "r"(cnt) : "memory")
#define MBAR_ARRIVE(addr) \
    asm volatile("mbarrier.arrive.shared.b64 _, [%0];" :: "r"(addr) : "memory")
#define CPASYNC_ARRIVE(addr) \
    asm volatile("cp.async.mbarrier.arrive.noinc.shared.b64 [%0];" :: "r"(addr) : "memory")
#define MBAR_WAIT(addr, parity) do {                                              \
    u32 _m = (addr), _p = (u32)(parity), _done;                                   \
    asm volatile("{\n\t.reg .pred p;\n\t"                                         \
        "mbarrier.try_wait.parity.acquire.cta.shared::cta.b64 p, [%1], %2;\n\t"   \
        "selp.b32 %0, 1, 0, p;\n\t}" : "=r"(_done) : "r"(_m), "r"(_p) : "memory");\
    if (!_done) {                                                                 \
        asm volatile("{\n\t.reg .pred P1;\n\t"                                    \
            "WL_%=:\n\t"                                                          \
            "mbarrier.try_wait.parity.acquire.cta.shared::cta.b64 P1, [%0], %1, 0x989680;\n\t" \
            "@P1 bra.uni WD_%=;\n\tbra.uni WL_%=;\n\tWD_%=:\n\t}"                 \
            :: "r"(_m), "r"(_p) : "memory");                                      \
    }                                                                             \
} while (0)

// ---------------------------------------------------------------------------
// Producer slot fill: 128 rows x 64 floats, 256B-per-row coalesced bursts
// ---------------------------------------------------------------------------
__device__ __forceinline__ void fill_slot(const float* __restrict__ db, u32 sb,
                                          int tile, int s, int h, int slot,
                                          int pt) {
    const u32 base = sb + OFF_STG + (u32)slot * STG_B;
    const int rowBase = tile * RB + h * 128;
    #pragma unroll
    for (int i = 0; i < 8; i++) {
        int idx = i * 256 + pt;             // 16 consecutive lanes = one 256B row
        int row = idx >> 4, u = idx & 15;
        int up = u ^ ((row & 1) << 2);
        long long gr = rowBase + row;
        if (gr > NDB - 1) gr = NDB - 1;
        const float* src = db + gr * (long long)DIM + s * 64 + u * 4;
        cp16(base + (u32)(row * 256 + up * 16), src);
    }
}

// ---------------------------------------------------------------------------
// Single fused warp-specialized persistent kernel
// ---------------------------------------------------------------------------
__global__ void __launch_bounds__(T, 1)
sim_kernel(const float* __restrict__ queries,
           const float* __restrict__ db,
           const int*   __restrict__ db_classes,
           const int*   __restrict__ y,
           float*       __restrict__ out) {
    extern __shared__ char smem[];
    const u32 sb = smem_u32(smem);
    const int t = threadIdx.x;
    const int w = t >> 5, lane = t & 31;
    const int rq = lane >> 2, c = lane & 3;
    const u32 xr = (u32)((rq & 1) << 2);

    u64*   skey = (u64*)(smem + OFF_SCR);                 // [16][8]
    float* ssum = (float*)(smem + OFF_SCR + 1024);        // [16][8]
    volatile int* tileRing = (volatile int*)(smem + OFF_SCR + 1536);  // [8]
    const u32 mb_full  = sb + OFF_SCR + 1600;             // 4 x 8B
    const u32 mb_empty = sb + OFF_SCR + 1632;             // 4 x 8B
    float* sinv = (float*)(smem + OFF_SCR + 1792);        // [16]
    volatile int* finFlag = (volatile int*)(smem + OFF_SCR + 1856);

    if (t == 0) {
        #pragma unroll
        for (int i = 0; i < 4; i++) {
            MBAR_INIT(mb_full + i * 8, 256u);    // producers: 256 noinc arrives
            MBAR_INIT(mb_empty + i * 8, 128u);   // consumers: 128 arrives
        }
    }
    __syncthreads();   // mbarrier init visible to all

    if (w >= 8) {
        // =================== PRODUCER (warps 8-15) ===================
        // starts immediately; consumers prep Q in parallel
        const int pt = t - 256;
        int ep0 = 1, ep1 = 1, ep2 = 1, ep3 = 1;
        int n = 0;
        for (;;) {
            if (t == 256) tileRing[n & 7] = (int)atomicAdd(&g_ctr, 1u);
            __threadfence_block();
            asm volatile("bar.sync 2, 256;" ::: "memory");
            int tile = tileRing[n & 7];
            if (tile >= NBLK) {
                MBAR_WAIT(mb_empty + 0, ep0);
                MBAR_ARRIVE(mb_full + 0);
                MBAR_WAIT(mb_empty + 8, ep1);
                MBAR_ARRIVE(mb_full + 8);
                break;
            }
            #pragma unroll 1
            for (int su = 0; su < NSTG; su += 2) {
                MBAR_WAIT(mb_empty + 0,  ep0); ep0 ^= 1;
                fill_slot(db, sb, tile, su,     0, 0, pt);
                CPASYNC_ARRIVE(mb_full + 0);
                MBAR_WAIT(mb_empty + 8,  ep1); ep1 ^= 1;
                fill_slot(db, sb, tile, su,     1, 1, pt);
                CPASYNC_ARRIVE(mb_full + 8);
                MBAR_WAIT(mb_empty + 16, ep2); ep2 ^= 1;
                fill_slot(db, sb, tile, su + 1, 0, 2, pt);
                CPASYNC_ARRIVE(mb_full + 16);
                MBAR_WAIT(mb_empty + 24, ep3); ep3 ^= 1;
                fill_slot(db, sb, tile, su + 1, 1, 3, pt);
                CPASYNC_ARRIVE(mb_full + 24);
            }
            n++;
        }
    } else {
        // =================== CONSUMER (warps 0-7) ===================
        // ---- Q prep (overlaps producer's first slot fills) ----
        #pragma unroll
        for (int rr = 0; rr < 2; rr++) {
            int r = w * 2 + rr;
            float acc = 0.f;
            const float4* qp = (const float4*)(queries + (size_t)r * DIM) + lane;
            #pragma unroll
            for (int it = 0; it < 8; it++) {
                float4 v = qp[it * 32];
                acc += v.x * v.x + v.y * v.y + v.z * v.z + v.w * v.w;
            }
            #pragma unroll
            for (int o = 16; o; o >>= 1) acc += __shfl_xor_sync(0xFFFFFFFFu, acc, o);
            if (lane == 0) sinv[r] = 1.f / (sqrtf(acc) + EPSV);
        }
        asm volatile("bar.sync 1, 256;" ::: "memory");
        #pragma unroll 1
        for (int r = 0; r < NQ; r++) {
            float4 v = *(const float4*)(queries + (size_t)r * DIM + t * 4);
            float iv = sinv[r];
            float x0 = v.x * iv, x1 = v.y * iv, x2 = v.z * iv, x3 = v.w * iv;
            u32 h0 = cvtpack(x1, x0), h1 = cvtpack(x3, x2);
            float e0 = x0 - lo2f(h0), e1 = x1 - hi2f(h0);
            float e2 = x2 - lo2f(h1), e3 = x3 - hi2f(h1);
            u32 l0 = cvtpack(e1, e0), l1 = cvtpack(e3, e2);
            char* dh = smem + r * QSTRIDE_B + t * 8;
            *(uint2*)dh            = make_uint2(h0, h1);
            *(uint2*)(dh + QMAT_B) = make_uint2(l0, l1);
        }
        asm volatile("bar.sync 1, 256;" ::: "memory");

        const int h = w >> 2;                   // row-half -> slot parity class
        const char* bh[2];
        const char* bl[2];
        bh[0] = smem + rq * QSTRIDE_B + c * 8;
        bh[1] = bh[0] + 8 * QSTRIDE_B;
        bl[0] = bh[0] + QMAT_B;
        bl[1] = bh[1] + QMAT_B;
        u32 rowoff[4];
        int rloc[4];
        #pragma unroll
        for (int i = 0; i < 4; i++) {
            rloc[i] = w * 32 + rq + i * 8;                    // tile-row
            rowoff[i] = (u32)((rloc[i] - h * 128) * 256);     // slot-local
        }
        const char* baseA = smem + OFF_STG + (size_t)h * STG_B;
        const char* baseB = baseA + 2 * STG_B;
        const u32 fullA  = mb_full  + (u32)h * 8;
        const u32 fullB  = fullA + 16;
        const u32 emptyA = mb_empty + (u32)h * 8;
        const u32 emptyB = emptyA + 16;
        int fpA = 0, fpB = 0;
        int n = 0;

        for (;;) {
            float d[2][2][4];
            float nrm[4] = {0.f, 0.f, 0.f, 0.f};
            #pragma unroll
            for (int m = 0; m < 2; m++)
                #pragma unroll
                for (int nt = 0; nt < 2; nt++)
                    #pragma unroll
                    for (int j = 0; j < 4; j++) d[m][nt][j] = 0.f;

            int tile = 0;
            #pragma unroll 1
            for (int s2 = 0; s2 < NSTG; s2 += 2) {
                MBAR_WAIT(fullA, fpA); fpA ^= 1;
                if (s2 == 0) {
                    tile = tileRing[n & 7];
                    if (tile >= NBLK) break;
                }
                #pragma unroll
                for (int half = 0; half < 2; half++) {
                    const char* A = half ? baseB : baseA;
                    const int s = s2 + half;
                    if (half) { MBAR_WAIT(fullB, fpB); fpB ^= 1; }
                    #pragma unroll
                    for (int j = 0; j < 4; j++) {
                        const int ch = s * 4 + j;
                        const u32 uoff = (u32)((((u32)(j * 4 + c)) ^ xr) * 16u);
                        float4 av[4];
                        #pragma unroll
                        for (int i = 0; i < 4; i++)
                            av[i] = *(const float4*)(A + rowoff[i] + uoff);
                        u32 ah[2][4], al[2][4];
                        #pragma unroll
                        for (int m = 0; m < 2; m++) {
                            float4 f = av[2 * m], g = av[2 * m + 1];
                            nrm[2 * m]     += f.x * f.x + f.y * f.y + f.z * f.z + f.w * f.w;
                            nrm[2 * m + 1] += g.x * g.x + g.y * g.y + g.z * g.z + g.w * g.w;
                            u32 fh0 = cvtpack(f.y, f.x), fh1 = cvtpack(f.w, f.z);
                            u32 gh0 = cvtpack(g.y, g.x), gh1 = cvtpack(g.w, g.z);
                            ah[m][0] = fh0; ah[m][1] = gh0; ah[m][2] = fh1; ah[m][3] = gh1;
                            float e0 = f.x - lo2f(fh0), e1 = f.y - hi2f(fh0);
                            float e2 = f.z - lo2f(fh1), e3 = f.w - hi2f(fh1);
                            float u0 = g.x - lo2f(gh0), u1 = g.y - hi2f(gh0);
                            float u2 = g.z - lo2f(gh1), u3 = g.w - hi2f(gh1);
                            al[m][0] = cvtpack(e1, e0); al[m][1] = cvtpack(u1, u0);
                            al[m][2] = cvtpack(e3, e2); al[m][3] = cvtpack(u3, u2);
                        }
                        #pragma unroll
                        for (int nt = 0; nt < 2; nt++) {
                            uint2 vh = *(const uint2*)(bh[nt] + ch * 32);
                            uint2 vl = *(const uint2*)(bl[nt] + ch * 32);
                            u32 bhf[2] = {vh.x, vh.y};
                            u32 blf[2] = {vl.x, vl.y};
                            #pragma unroll
                            for (int m = 0; m < 2; m++) {
                                mma16816(d[m][nt], ah[m], bhf);
                                mma16816(d[m][nt], ah[m], blf);
                                mma16816(d[m][nt], al[m], bhf);
                            }
                        }
                    }
                    MBAR_ARRIVE(half ? emptyB : emptyA);
                }
            }
            if (tile >= NBLK) break;

            // ---- epilogue (consumer-only named barrier) ----
            float inv[4];
            #pragma unroll
            for (int j = 0; j < 4; j++) {
                float nn = nrm[j];
                nn += __shfl_xor_sync(0xFFFFFFFFu, nn, 1);
                nn += __shfl_xor_sync(0xFFFFFFFFu, nn, 2);
                inv[j] = 1.f / (sqrtf(nn) + EPSV);
            }
            int  grow[4];
            bool valid[4];
            #pragma unroll
            for (int j = 0; j < 4; j++) {
                grow[j] = tile * RB + rloc[j];
                valid[j] = grow[j] < NDB;
            }
            #pragma unroll
            for (int nt = 0; nt < 2; nt++)
                #pragma unroll
                for (int j = 0; j < 2; j++) {
                    int q = nt * 8 + 2 * c + j;
                    float s0 = d[0][nt][j]     * inv[0];
                    float s1 = d[0][nt][2 + j] * inv[1];
                    float s2v = d[1][nt][j]     * inv[2];
                    float s3 = d[1][nt][2 + j] * inv[3];
                    u64 kb = 0ull; float sm = 0.f;
                    if (valid[0]) { u64 k = pack_key(s0, grow[0]); if (k > kb) kb = k; sm += s0; }
                    if (valid[1]) { u64 k = pack_key(s1, grow[1]); if (k > kb) kb = k; sm += s1; }
                    if (valid[2]) { u64 k = pack_key(s2v, grow[2]); if (k > kb) kb = k; sm += s2v; }
                    if (valid[3]) { u64 k = pack_key(s3, grow[3]); if (k > kb) kb = k; sm += s3; }
                    #pragma unroll
                    for (int o = 4; o <= 16; o <<= 1) {
                        u64   ok = __shfl_xor_sync(0xFFFFFFFFu, kb, o);
                        float os = __shfl_xor_sync(0xFFFFFFFFu, sm, o);
                        if (ok > kb) kb = ok;
                        sm += os;
                    }
                    if (rq == 0) { skey[q * 8 + w] = kb; ssum[q * 8 + w] = sm; }
                }
            asm volatile("bar.sync 1, 256;" ::: "memory");
            if (t < 128) {
                int q = t >> 3, w2 = t & 7;
                u64 kb = skey[q * 8 + w2];
                float sm = ssum[q * 8 + w2];
                #pragma unroll
                for (int o = 4; o; o >>= 1) {
                    u64   ok = __shfl_down_sync(0xFFFFFFFFu, kb, o, 8);
                    float os = __shfl_down_sync(0xFFFFFFFFu, sm, o, 8);
                    if (ok > kb) kb = ok;
                    sm += os;
                }
                if (w2 == 0) {
                    g_pkey[(size_t)tile * NQ + q] = kb;
                    g_psum[(size_t)tile * NQ + q] = sm;
                }
            }
            asm volatile("bar.sync 1, 256;" ::: "memory");
            n++;
        }
    }

    // =================== completion + fused finalize ===================
    __syncthreads();
    __threadfence();
    if (t == 0) {
        unsigned old = atomicAdd(&g_done, 1u);
        finFlag[0] = (old == GRID - 1) ? 1 : 0;
    }
    __syncthreads();
    if (!finFlag[0]) return;
    __threadfence();    // acquire: all CTAs' partials visible

    {
        u64*   fkey = (u64*)(smem + OFF_SCR);          // reuse scratch
        float* fsum = (float*)(smem + OFF_SCR + 256);
        int*   fcls = (int*)(smem + OFF_SCR + 384);
        const int pt = t - 256;
        if (t >= 256) {                                 // producer threads (low-reg)
            const int q = pt >> 4, sub = pt & 15;
            u64 kb = 0ull; float sm = 0.f;
            for (int i = sub; i < NBLK; i += 16) {
                u64 k = g_pkey[(size_t)i * NQ + q];
                if (k > kb) kb = k;
                sm += g_psum[(size_t)i * NQ + q];
            }
            #pragma unroll
            for (int o = 8; o; o >>= 1) {
                u64   ok = __shfl_down_sync(0xFFFFFFFFu, kb, o, 16);
                float os = __shfl_down_sync(0xFFFFFFFFu, sm, o, 16);
                if (ok > kb) kb = ok;
                sm += os;
            }
            if (sub == 0) { fkey[q] = kb; fsum[q] = sm; }
        }
        __syncthreads();
        if (t >= 256 && pt < NQ) {
            u64 k = fkey[pt];
            unsigned idx = ~((unsigned)k);
            unsigned o   = (unsigned)(k >> 32);
            unsigned fb  = (o & 0x80000000u) ? (o & 0x7FFFFFFFu) : ~o;
            float mx = __uint_as_float(fb);
            int cls = db_classes[idx];
            out[pt]          = mx;
            out[NQ + pt]     = fsum[pt] / (float)NDB;
            out[2 * NQ + pt] = (float)cls;
            fcls[pt] = cls;
        }
        __syncthreads();
        if (t == 256) {
            int cnt = 0;
            #pragma unroll
            for (int i = 0; i < NQ; i++) cnt += (fcls[i] == y[i]) ? 1 : 0;
            out[3 * NQ] = (float)cnt / (float)NQ;
            // reset counters for the next graph replay (deterministic)
            g_ctr  = 0;
            g_done = 0;
        }
    }
}

// ---------------------------------------------------------------------------
// kernel_launch
// ---------------------------------------------------------------------------
extern "C" void kernel_launch(void* const* d_in, const int* in_sizes, int n_in,
                              void* d_out, int out_size) {
    const float* queries    = (const float*)d_in[0];
    const float* database   = (const float*)d_in[1];
    const int*   db_classes = (const int*)d_in[2];
    const int*   y          = (const int*)d_in[3];
    float* out = (float*)d_out;

    cudaFuncSetAttribute(sim_kernel,
                         cudaFuncAttributeMaxDynamicSharedMemorySize,
                         SMEM_TOTAL);

    sim_kernel<<<GRID, T, SMEM_TOTAL>>>(queries, database, db_classes, y, out);
}